// round 5
// baseline (speedup 1.0000x reference)
#include <cuda_runtime.h>
#include <stdint.h>

// Problem constants (fixed by the reference: B=64, T=2048, D=64, V=100000)
#define BB 64
#define TT 2048
#define DD 64
#define NROWS (4 * BB)          // 4 features x 64 batches
#define BT (BB * TT)            // 131072

// Output layout (floats), tuple flattened in order:
//   features [B,T,256] @ 0
//   times    [B,T]     @ BT*256
//   delta    [B,T,256] @ BT*256 + BT
//   mask     [B,T,256] @ BT*256 + BT + BT*256
#define OFF_TIMES  (BT * 256)                 // 33554432
#define OFF_DELTA  (OFF_TIMES + BT)           // 33685504
#define OFF_MASK   (OFF_DELTA + BT * 256)     // 67239936

// Output lines with gw < RESIDENT_CUT in the mask region are written with
// default (write-back) stores so they stay dirty-resident in L2 across graph
// replays (67 MB; + 51 MB E-tables = 118 MB < 126 MB L2). Everything else is
// __stcs (evict-first) to protect that resident set.
#define RESIDENT_CUT (BT / 2)

// Scratch for the beta recurrence results: [4][B][T]
__device__ float g_beta[4 * BT];

// ---------------------------------------------------------------------------
// Kernel 1: beta linear-recurrence scan, block-per-row two-level scan.
// x_t = a_t * x_{t-1} + c_t, with a_t = m_{t-1}*p_t, c_t = dt_t*p_t, x_0 = 0.
// ---------------------------------------------------------------------------
__device__ __forceinline__ void load_elem(int f, int t, const float* tr,
                                          const int* c1r, const int* c2r,
                                          const float* n1r, const float* n2r,
                                          float& a, float& c)
{
    if (t == 0) { a = 0.0f; c = 0.0f; return; }
    const float tc = tr[t];
    const float dt = tc - tr[t - 1];
    const float p  = (tc != -1.0f) ? 1.0f : 0.0f;
    float m;
    if (f == 0)      { const int   v = __ldg(c1r + t - 1); m = (v != 0 && v != -1) ? 1.0f : 0.0f; }
    else if (f == 1) { const int   v = __ldg(c2r + t - 1); m = (v != 0 && v != -1) ? 1.0f : 0.0f; }
    else if (f == 2) { const float v = __ldg(n1r + t - 1); m = (v != 0.0f && v != -1.0f) ? 1.0f : 0.0f; }
    else             { const float v = __ldg(n2r + t - 1); m = (v != 0.0f && v != -1.0f) ? 1.0f : 0.0f; }
    a = m * p;
    c = dt * p;
}

__global__ __launch_bounds__(1024) void beta_scan_kernel(
    const int*   __restrict__ cat1,
    const int*   __restrict__ cat2,
    const float* __restrict__ num1,
    const float* __restrict__ num2,
    const float* __restrict__ times)
{
    const int row  = blockIdx.x;        // 0..255
    const int f    = row >> 6;          // 0..3
    const int b    = row & 63;          // 0..63
    const int tid  = threadIdx.x;       // 0..1023
    const int lane = tid & 31;
    const int wid  = tid >> 5;          // 0..31

    __shared__ float sA[32], sC[32];

    const float* tr  = times + b * TT;
    const int*   c1r = cat1  + b * TT;
    const int*   c2r = cat2  + b * TT;
    const float* n1r = num1  + b * TT;
    const float* n2r = num2  + b * TT;

    const int t0 = tid * 2;
    float a0, c0, a1, c1;
    load_elem(f, t0,     tr, c1r, c2r, n1r, n2r, a0, c0);
    load_elem(f, t0 + 1, tr, c1r, c2r, n1r, n2r, a1, c1);

    // Pair composition (apply t0 then t1)
    float A = a1 * a0;
    float C = c1 + a1 * c0;

    // Warp inclusive scan of pair-compositions
    #pragma unroll
    for (int off = 1; off < 32; off <<= 1) {
        const float Ap = __shfl_up_sync(0xffffffffu, A, off);
        const float Cp = __shfl_up_sync(0xffffffffu, C, off);
        if (lane >= off) {
            C = C + A * Cp;
            A = A * Ap;
        }
    }

    if (lane == 31) { sA[wid] = A; sC[wid] = C; }
    __syncthreads();

    if (wid == 0) {
        float Aw = sA[lane], Cw = sC[lane];
        #pragma unroll
        for (int off = 1; off < 32; off <<= 1) {
            const float Ap = __shfl_up_sync(0xffffffffu, Aw, off);
            const float Cp = __shfl_up_sync(0xffffffffu, Cw, off);
            if (lane >= off) {
                Cw = Cw + Aw * Cp;
                Aw = Aw * Ap;
            }
        }
        float Ae = __shfl_up_sync(0xffffffffu, Aw, 1);
        float Ce = __shfl_up_sync(0xffffffffu, Cw, 1);
        if (lane == 0) { Ae = 1.0f; Ce = 0.0f; }
        sA[lane] = Ae; sC[lane] = Ce;
    }
    __syncthreads();

    float Ax = __shfl_up_sync(0xffffffffu, A, 1);
    float Cx = __shfl_up_sync(0xffffffffu, C, 1);
    if (lane == 0) { Ax = 1.0f; Cx = 0.0f; }

    const float Cw = sC[wid];
    const float xpre = Cx + Ax * Cw;

    const float x0v = c0 + a0 * xpre;
    const float x1v = c1 + a1 * x0v;

    float* br = g_beta + (size_t)row * TT;
    br[t0]     = x0v;
    br[t0 + 1] = x1v;
}

// ---------------------------------------------------------------------------
// Kernel 2: emit all outputs. One warp per (b,t) (R2 structure — proven best).
// Streaming (__stcs) stores everywhere EXCEPT the mask region for
// gw < RESIDENT_CUT, which uses default write-back stores so those 67 MB stay
// dirty-resident in L2 across graph replays (no DRAM write traffic for them
// in steady state).
// ---------------------------------------------------------------------------
__global__ void emit_kernel(const int*   __restrict__ cat1,
                            const int*   __restrict__ cat2,
                            const float* __restrict__ num1,
                            const float* __restrict__ num2,
                            const float* __restrict__ times,
                            const float* __restrict__ E1,
                            const float* __restrict__ E2,
                            const float* __restrict__ w1,
                            const float* __restrict__ b1,
                            const float* __restrict__ w2,
                            const float* __restrict__ b2,
                            float* __restrict__ out)
{
    const int gw   = blockIdx.x * (blockDim.x >> 5) + (threadIdx.x >> 5); // (b,t)
    const int lane = threadIdx.x & 31;
    if (gw >= BT) return;

    const int   c1 = __ldg(cat1 + gw);
    const int   c2 = __ldg(cat2 + gw);
    const float n1 = __ldg(num1 + gw);
    const float n2 = __ldg(num2 + gw);
    const float tm = __ldg(times + gw);

    const float be0 = g_beta[0 * BT + gw];
    const float be1 = g_beta[1 * BT + gw];
    const float be2 = g_beta[2 * BT + gw];
    const float be3 = g_beta[3 * BT + gw];

    const float mk0 = (c1 != 0 && c1 != -1)       ? 1.0f : 0.0f;
    const float mk1 = (c2 != 0 && c2 != -1)       ? 1.0f : 0.0f;
    const float mk2 = (n1 != 0.0f && n1 != -1.0f) ? 1.0f : 0.0f;
    const float mk3 = (n2 != 0.0f && n2 != -1.0f) ? 1.0f : 0.0f;

    const float4* e1row = reinterpret_cast<const float4*>(E1 + (size_t)c1 * DD);
    const float4* e2row = reinterpret_cast<const float4*>(E2 + (size_t)c2 * DD);
    const float4* w1v = reinterpret_cast<const float4*>(w1);
    const float4* b1v = reinterpret_cast<const float4*>(b1);
    const float4* w2v = reinterpret_cast<const float4*>(w2);
    const float4* b2v = reinterpret_cast<const float4*>(b2);

    float4* feat4  = reinterpret_cast<float4*>(out) + (size_t)gw * 64;
    float4* delta4 = reinterpret_cast<float4*>(out + OFF_DELTA) + (size_t)gw * 64;
    float4* mask4  = reinterpret_cast<float4*>(out + OFF_MASK)  + (size_t)gw * 64;

    const bool resident = (gw < RESIDENT_CUT);

    const float betas[4] = {be0, be1, be2, be3};
    const float msks[4]  = {mk0, mk1, mk2, mk3};

    #pragma unroll
    for (int half = 0; half < 2; ++half) {
        const int j = lane + half * 32;
        float4 v;
        if (j < 16) {
            v = __ldg(e1row + j);
        } else if (j < 32) {
            v = __ldg(e2row + (j - 16));
        } else if (j < 48) {
            const float4 w = __ldg(w1v + (j - 32));
            const float4 o = __ldg(b1v + (j - 32));
            v = make_float4(fmaf(n1, w.x, o.x), fmaf(n1, w.y, o.y),
                            fmaf(n1, w.z, o.z), fmaf(n1, w.w, o.w));
        } else {
            const float4 w = __ldg(w2v + (j - 48));
            const float4 o = __ldg(b2v + (j - 48));
            v = make_float4(fmaf(n2, w.x, o.x), fmaf(n2, w.y, o.y),
                            fmaf(n2, w.z, o.z), fmaf(n2, w.w, o.w));
        }
        __stcs(feat4 + j, v);

        const int fidx = j >> 4;
        const float bv = betas[fidx];
        const float mv = msks[fidx];
        __stcs(delta4 + j, make_float4(bv, bv, bv, bv));

        const float4 mval = make_float4(mv, mv, mv, mv);
        if (resident) {
            mask4[j] = mval;                 // default write-back: stays in L2
        } else {
            __stcs(mask4 + j, mval);         // streaming: evict-first
        }
    }

    if (lane == 0) {
        __stcs(out + OFF_TIMES + gw, tm);
    }
}

// ---------------------------------------------------------------------------
// Launch
// Inputs (metadata order): cat1, cat2, num1, num2, event_time, E1, E2,
//                          w1, b1, w2, b2
// ---------------------------------------------------------------------------
extern "C" void kernel_launch(void* const* d_in, const int* in_sizes, int n_in,
                              void* d_out, int out_size)
{
    const int*   cat1  = (const int*)  d_in[0];
    const int*   cat2  = (const int*)  d_in[1];
    const float* num1  = (const float*)d_in[2];
    const float* num2  = (const float*)d_in[3];
    const float* times = (const float*)d_in[4];
    const float* E1    = (const float*)d_in[5];
    const float* E2    = (const float*)d_in[6];
    const float* w1    = (const float*)d_in[7];
    const float* b1    = (const float*)d_in[8];
    const float* w2    = (const float*)d_in[9];
    const float* b2    = (const float*)d_in[10];
    float* out = (float*)d_out;

    // Kernel 1: one 1024-thread block per (f,b) row
    beta_scan_kernel<<<NROWS, 1024>>>(cat1, cat2, num1, num2, times);

    // Kernel 2: one warp per (b,t): 131072 warps, 8 warps/block
    emit_kernel<<<BT / 8, 256>>>(cat1, cat2, num1, num2, times,
                                 E1, E2, w1, b1, w2, b2, out);
}

// round 6
// speedup vs baseline: 1.0550x; 1.0550x over previous
#include <cuda_runtime.h>
#include <stdint.h>

// Problem constants (fixed by the reference: B=64, T=2048, D=64, V=100000)
#define BB 64
#define TT 2048
#define DD 64
#define NROWS (4 * BB)          // 4 features x 64 batches
#define BT (BB * TT)            // 131072

// Output layout (floats), tuple flattened in order:
//   features [B,T,256] @ 0
//   times    [B,T]     @ BT*256
//   delta    [B,T,256] @ BT*256 + BT
//   mask     [B,T,256] @ BT*256 + BT + BT*256
#define OFF_TIMES  (BT * 256)                 // 33554432
#define OFF_DELTA  (OFF_TIMES + BT)           // 33685504
#define OFF_MASK   (OFF_DELTA + BT * 256)     // 67239936

// Scratch for the beta recurrence results: [4][B][T]
__device__ float g_beta[4 * BT];

// ---------------------------------------------------------------------------
// Kernel 1: beta linear-recurrence scan, block-per-row two-level scan.
// x_t = a_t * x_{t-1} + c_t, with a_t = m_{t-1}*p_t, c_t = dt_t*p_t, x_0 = 0.
// ---------------------------------------------------------------------------
__device__ __forceinline__ void load_elem(int f, int t, const float* tr,
                                          const int* c1r, const int* c2r,
                                          const float* n1r, const float* n2r,
                                          float& a, float& c)
{
    if (t == 0) { a = 0.0f; c = 0.0f; return; }
    const float tc = tr[t];
    const float dt = tc - tr[t - 1];
    const float p  = (tc != -1.0f) ? 1.0f : 0.0f;
    float m;
    if (f == 0)      { const int   v = __ldg(c1r + t - 1); m = (v != 0 && v != -1) ? 1.0f : 0.0f; }
    else if (f == 1) { const int   v = __ldg(c2r + t - 1); m = (v != 0 && v != -1) ? 1.0f : 0.0f; }
    else if (f == 2) { const float v = __ldg(n1r + t - 1); m = (v != 0.0f && v != -1.0f) ? 1.0f : 0.0f; }
    else             { const float v = __ldg(n2r + t - 1); m = (v != 0.0f && v != -1.0f) ? 1.0f : 0.0f; }
    a = m * p;
    c = dt * p;
}

__global__ __launch_bounds__(1024) void beta_scan_kernel(
    const int*   __restrict__ cat1,
    const int*   __restrict__ cat2,
    const float* __restrict__ num1,
    const float* __restrict__ num2,
    const float* __restrict__ times)
{
    const int row  = blockIdx.x;        // 0..255
    const int f    = row >> 6;          // 0..3
    const int b    = row & 63;          // 0..63
    const int tid  = threadIdx.x;       // 0..1023
    const int lane = tid & 31;
    const int wid  = tid >> 5;          // 0..31

    __shared__ float sA[32], sC[32];

    const float* tr  = times + b * TT;
    const int*   c1r = cat1  + b * TT;
    const int*   c2r = cat2  + b * TT;
    const float* n1r = num1  + b * TT;
    const float* n2r = num2  + b * TT;

    const int t0 = tid * 2;
    float a0, c0, a1, c1;
    load_elem(f, t0,     tr, c1r, c2r, n1r, n2r, a0, c0);
    load_elem(f, t0 + 1, tr, c1r, c2r, n1r, n2r, a1, c1);

    // Pair composition (apply t0 then t1)
    float A = a1 * a0;
    float C = c1 + a1 * c0;

    // Warp inclusive scan of pair-compositions
    #pragma unroll
    for (int off = 1; off < 32; off <<= 1) {
        const float Ap = __shfl_up_sync(0xffffffffu, A, off);
        const float Cp = __shfl_up_sync(0xffffffffu, C, off);
        if (lane >= off) {
            C = C + A * Cp;
            A = A * Ap;
        }
    }

    if (lane == 31) { sA[wid] = A; sC[wid] = C; }
    __syncthreads();

    if (wid == 0) {
        float Aw = sA[lane], Cw = sC[lane];
        #pragma unroll
        for (int off = 1; off < 32; off <<= 1) {
            const float Ap = __shfl_up_sync(0xffffffffu, Aw, off);
            const float Cp = __shfl_up_sync(0xffffffffu, Cw, off);
            if (lane >= off) {
                Cw = Cw + Aw * Cp;
                Aw = Aw * Ap;
            }
        }
        float Ae = __shfl_up_sync(0xffffffffu, Aw, 1);
        float Ce = __shfl_up_sync(0xffffffffu, Cw, 1);
        if (lane == 0) { Ae = 1.0f; Ce = 0.0f; }
        sA[lane] = Ae; sC[lane] = Ce;
    }
    __syncthreads();

    float Ax = __shfl_up_sync(0xffffffffu, A, 1);
    float Cx = __shfl_up_sync(0xffffffffu, C, 1);
    if (lane == 0) { Ax = 1.0f; Cx = 0.0f; }

    const float Cw = sC[wid];
    const float xpre = Cx + Ax * Cw;

    const float x0v = c0 + a0 * xpre;
    const float x1v = c1 + a1 * x0v;

    float* br = g_beta + (size_t)row * TT;
    br[t0]     = x0v;
    br[t0 + 1] = x1v;
}

// ---------------------------------------------------------------------------
// Kernel 2: emit all outputs. One warp per (b,t). Branchless lane-selects
// (no intra-warp divergence), all loads batched before the store burst.
// __stcs (evict-first) on all output stores so the E1/E2 tables stay L2-hot.
// ---------------------------------------------------------------------------
__global__ void emit_kernel(const int*   __restrict__ cat1,
                            const int*   __restrict__ cat2,
                            const float* __restrict__ num1,
                            const float* __restrict__ num2,
                            const float* __restrict__ times,
                            const float* __restrict__ E1,
                            const float* __restrict__ E2,
                            const float* __restrict__ w1,
                            const float* __restrict__ b1,
                            const float* __restrict__ w2,
                            const float* __restrict__ b2,
                            float* __restrict__ out)
{
    const int gw   = blockIdx.x * (blockDim.x >> 5) + (threadIdx.x >> 5); // (b,t)
    const int lane = threadIdx.x & 31;
    if (gw >= BT) return;

    const bool lo = (lane < 16);
    const int  sl = lo ? lane : (lane - 16);   // sub-lane within 16

    // --- batch all scalar loads (independent, high MLP) ---
    const int   c1 = __ldg(cat1 + gw);
    const int   c2 = __ldg(cat2 + gw);
    const float n1 = __ldg(num1 + gw);
    const float n2 = __ldg(num2 + gw);
    const float tm = __ldg(times + gw);

    const float be0 = g_beta[0 * BT + gw];
    const float be1 = g_beta[1 * BT + gw];
    const float be2 = g_beta[2 * BT + gw];
    const float be3 = g_beta[3 * BT + gw];

    // --- half 0 gather: lanes 0-15 -> E1 row, lanes 16-31 -> E2 row ---
    const float4* e1row = reinterpret_cast<const float4*>(E1 + (size_t)c1 * DD);
    const float4* e2row = reinterpret_cast<const float4*>(E2 + (size_t)c2 * DD);
    const float4* src0  = lo ? (e1row + sl) : (e2row + sl);
    const float4  v0    = __ldg(src0);

    // --- half 1: lanes 0-15 -> n1*w1+b1, lanes 16-31 -> n2*w2+b2 ---
    const float4* wsrc = lo ? (reinterpret_cast<const float4*>(w1) + sl)
                            : (reinterpret_cast<const float4*>(w2) + sl);
    const float4* osrc = lo ? (reinterpret_cast<const float4*>(b1) + sl)
                            : (reinterpret_cast<const float4*>(b2) + sl);
    const float4 wv = __ldg(wsrc);
    const float4 ov = __ldg(osrc);
    const float  nn = lo ? n1 : n2;
    const float4 v1 = make_float4(fmaf(nn, wv.x, ov.x), fmaf(nn, wv.y, ov.y),
                                  fmaf(nn, wv.z, ov.z), fmaf(nn, wv.w, ov.w));

    // --- delta / mask lane values (SELs, no branches) ---
    const float mk0 = (c1 != 0 && c1 != -1)       ? 1.0f : 0.0f;
    const float mk1 = (c2 != 0 && c2 != -1)       ? 1.0f : 0.0f;
    const float mk2 = (n1 != 0.0f && n1 != -1.0f) ? 1.0f : 0.0f;
    const float mk3 = (n2 != 0.0f && n2 != -1.0f) ? 1.0f : 0.0f;

    const float bv0 = lo ? be0 : be1;   // half 0: features 0,1
    const float bv1 = lo ? be2 : be3;   // half 1: features 2,3
    const float mv0 = lo ? mk0 : mk1;
    const float mv1 = lo ? mk2 : mk3;

    // --- store burst (all data ready; 7 independent STG.128 streams) ---
    float4* feat4  = reinterpret_cast<float4*>(out) + (size_t)gw * 64;
    float4* delta4 = reinterpret_cast<float4*>(out + OFF_DELTA) + (size_t)gw * 64;
    float4* mask4  = reinterpret_cast<float4*>(out + OFF_MASK)  + (size_t)gw * 64;

    __stcs(feat4 + lane,       v0);
    __stcs(feat4 + lane + 32,  v1);
    __stcs(delta4 + lane,      make_float4(bv0, bv0, bv0, bv0));
    __stcs(delta4 + lane + 32, make_float4(bv1, bv1, bv1, bv1));
    __stcs(mask4 + lane,       make_float4(mv0, mv0, mv0, mv0));
    __stcs(mask4 + lane + 32,  make_float4(mv1, mv1, mv1, mv1));

    if (lane == 0) {
        __stcs(out + OFF_TIMES + gw, tm);
    }
}

// ---------------------------------------------------------------------------
// Launch
// Inputs (metadata order): cat1, cat2, num1, num2, event_time, E1, E2,
//                          w1, b1, w2, b2
// ---------------------------------------------------------------------------
extern "C" void kernel_launch(void* const* d_in, const int* in_sizes, int n_in,
                              void* d_out, int out_size)
{
    const int*   cat1  = (const int*)  d_in[0];
    const int*   cat2  = (const int*)  d_in[1];
    const float* num1  = (const float*)d_in[2];
    const float* num2  = (const float*)d_in[3];
    const float* times = (const float*)d_in[4];
    const float* E1    = (const float*)d_in[5];
    const float* E2    = (const float*)d_in[6];
    const float* w1    = (const float*)d_in[7];
    const float* b1    = (const float*)d_in[8];
    const float* w2    = (const float*)d_in[9];
    const float* b2    = (const float*)d_in[10];
    float* out = (float*)d_out;

    // Kernel 1: one 1024-thread block per (f,b) row
    beta_scan_kernel<<<NROWS, 1024>>>(cat1, cat2, num1, num2, times);

    // Kernel 2: one warp per (b,t): 131072 warps, 8 warps/block
    emit_kernel<<<BT / 8, 256>>>(cat1, cat2, num1, num2, times,
                                 E1, E2, w1, b1, w2, b2, out);
}